// round 1
// baseline (speedup 1.0000x reference)
#include <cuda_runtime.h>
#include <math.h>

#define BB 8
#define IMG 256
#define INCH 2
#define PSZ 16
#define EE 256
#define DEPTH 8
#define HPN 16
#define LL 256
#define DI 512
#define DS 16
#define DTRN 16
#define DCN 4
#define NTOK 2048          // B*L
#define XZW 1024           // 2*DI

// ---------------- scratch (static device globals; no allocation) ----------------
__device__ float g_temb[BB*EE];
__device__ float g_h[NTOK*EE];
__device__ float g_hn[NTOK*EE];
__device__ float g_patches[NTOK*512];
__device__ float g_xz[NTOK*XZW];
__device__ float g_u[NTOK*DI];
__device__ float g_dbc[NTOK*48];
__device__ float g_dt[NTOK*DI];
__device__ float g_y[NTOK*DI];
__device__ float g_yg[NTOK*DI];
__device__ float g_feat[BB*EE*HPN*HPN];
__device__ float g_d1[BB*128*32*32];
__device__ float g_d2[BB*64*64*64];
__device__ float g_d3[BB*32*128*128];

__device__ __forceinline__ float geluf(float v){ return 0.5f*v*(1.0f+erff(v*0.70710678118654752f)); }
__device__ __forceinline__ float siluf(float v){ return v/(1.0f+expf(-v)); }

// ---------------- time embedding: B blocks of 256 threads ----------------
__global__ void time_emb_kernel(const int* __restrict__ t, const float* __restrict__ w1,
                                const float* __restrict__ b1, const float* __restrict__ w2,
                                const float* __restrict__ b2){
  __shared__ float hdn[EE];
  int b = blockIdx.x; int j = threadIdx.x;
  float tf = (float)t[b];
  hdn[j] = geluf(tf*w1[j] + b1[j]);
  __syncthreads();
  float acc = b2[j];
  #pragma unroll 8
  for (int k=0;k<EE;k++) acc = fmaf(hdn[k], w2[k*EE + j], acc);
  g_temb[b*EE + j] = acc;
}

// ---------------- im2col patch gather: (b,l,k) k=c*256+p*16+q ----------------
__global__ void patch_gather_kernel(const float* __restrict__ x){
  int idx = blockIdx.x*blockDim.x + threadIdx.x;
  int k = idx & 511; int tok = idx >> 9;
  int l = tok & (LL-1); int b = tok >> 8;
  int c = k >> 8; int rem = k & 255; int p = rem >> 4; int q = rem & 15;
  int hp = l >> 4; int wp = l & 15;
  g_patches[idx] = x[(((size_t)(b*INCH + c))*IMG + hp*PSZ + p)*IMG + wp*PSZ + q];
}

// ---------------- generic GEMM: C[m,n] = sum_k A[m,k]*Bw[n,k] (+bias[n]) (+addsrc[m,n]) ----
#define GBM 64
#define GBN 64
#define GBK 16
__global__ void gemm_nt_kernel(const float* __restrict__ A, const float* __restrict__ Bw,
                               const float* __restrict__ addsrc, const float* __restrict__ bias,
                               float* __restrict__ C, int M, int N, int K){
  __shared__ float As[GBK][GBM];
  __shared__ float Bs[GBK][GBN];
  int tid = threadIdx.x;
  int tx = tid & 15, ty = tid >> 4;
  int m0 = blockIdx.y*GBM, n0 = blockIdx.x*GBN;
  int lr = tid >> 2;            // 0..63 row within tile
  int lk = (tid & 3) << 2;      // 0,4,8,12
  float acc[4][4];
  #pragma unroll
  for (int i=0;i<4;i++)
    #pragma unroll
    for (int j=0;j<4;j++) acc[i][j]=0.f;

  for (int k0=0;k0<K;k0+=GBK){
    int gm = m0 + lr;
    float4 va = make_float4(0.f,0.f,0.f,0.f);
    if (gm < M) va = *(const float4*)(A + (size_t)gm*K + k0 + lk);
    As[lk+0][lr]=va.x; As[lk+1][lr]=va.y; As[lk+2][lr]=va.z; As[lk+3][lr]=va.w;
    int gn = n0 + lr;
    float4 vb = make_float4(0.f,0.f,0.f,0.f);
    if (gn < N) vb = *(const float4*)(Bw + (size_t)gn*K + k0 + lk);
    Bs[lk+0][lr]=vb.x; Bs[lk+1][lr]=vb.y; Bs[lk+2][lr]=vb.z; Bs[lk+3][lr]=vb.w;
    __syncthreads();
    #pragma unroll
    for (int k=0;k<GBK;k++){
      float4 a4 = *(const float4*)&As[k][ty<<2];
      float4 b4 = *(const float4*)&Bs[k][tx<<2];
      float av[4]={a4.x,a4.y,a4.z,a4.w};
      float bv[4]={b4.x,b4.y,b4.z,b4.w};
      #pragma unroll
      for (int i=0;i<4;i++)
        #pragma unroll
        for (int j=0;j<4;j++) acc[i][j] = fmaf(av[i], bv[j], acc[i][j]);
    }
    __syncthreads();
  }
  #pragma unroll
  for (int i=0;i<4;i++){
    int gm = m0 + (ty<<2) + i;
    if (gm >= M) continue;
    #pragma unroll
    for (int j=0;j<4;j++){
      int gn = n0 + (tx<<2) + j;
      if (gn >= N) continue;
      float v = acc[i][j];
      if (bias)   v += bias[gn];
      if (addsrc) v += addsrc[(size_t)gm*N + gn];
      C[(size_t)gm*N + gn] = v;
    }
  }
}

// ---------------- h += pos + temb ----------------
__global__ void addpos_kernel(const float* __restrict__ pos){
  int idx = blockIdx.x*blockDim.x + threadIdx.x;  // NTOK*EE
  int e = idx & 255; int tok = idx >> 8; int l = tok & 255; int b = tok >> 8;
  g_h[idx] += pos[l*EE + e] + g_temb[b*EE + e];
}

// ---------------- LayerNorm: block per token ----------------
__global__ void ln_kernel(const float* __restrict__ g, const float* __restrict__ bta){
  __shared__ float ss[8], ssq[8], mv[2];
  int tok = blockIdx.x;
  float v = g_h[(size_t)tok*EE + threadIdx.x];
  float s = v, sq = v*v;
  #pragma unroll
  for (int m=16;m;m>>=1){ s += __shfl_xor_sync(0xffffffffu, s, m); sq += __shfl_xor_sync(0xffffffffu, sq, m); }
  int w = threadIdx.x >> 5;
  if ((threadIdx.x & 31) == 0){ ss[w]=s; ssq[w]=sq; }
  __syncthreads();
  if (threadIdx.x == 0){
    float a=0.f, bq=0.f;
    #pragma unroll
    for (int i=0;i<8;i++){ a+=ss[i]; bq+=ssq[i]; }
    float mean = a*(1.f/EE);
    float var  = bq*(1.f/EE) - mean*mean;
    mv[0]=mean; mv[1]=rsqrtf(var + 1e-5f);
  }
  __syncthreads();
  g_hn[(size_t)tok*EE + threadIdx.x] = (v - mv[0])*mv[1]*g[threadIdx.x] + bta[threadIdx.x];
}

// ---------------- causal conv (DC=4) + SiLU on u-half of xz ----------------
__global__ void conv_silu_kernel(const float* __restrict__ w, const float* __restrict__ bias){
  int idx = blockIdx.x*blockDim.x + threadIdx.x;  // NTOK*DI
  int d = idx & (DI-1); int tok = idx >> 9; int l = tok & 255; int b = tok >> 8;
  float acc = bias[d];
  #pragma unroll
  for (int j=0;j<DCN;j++){
    int ls = l + j - (DCN-1);
    if (ls >= 0) acc = fmaf(g_xz[((size_t)(b*LL + ls))*XZW + d], w[d*DCN + j], acc);
  }
  g_u[idx] = siluf(acc);
}

// ---------------- dt = softplus(dbc[:,:16] @ dt_w.T + dt_b) ----------------
__global__ void dt_kernel(const float* __restrict__ dtw, const float* __restrict__ dtb){
  int idx = blockIdx.x*blockDim.x + threadIdx.x;  // NTOK*DI
  int d = idx & (DI-1); int tok = idx >> 9;
  const float* db = &g_dbc[(size_t)tok*48];
  float acc = dtb[d];
  #pragma unroll
  for (int r=0;r<DTRN;r++) acc = fmaf(db[r], dtw[d*DTRN + r], acc);
  g_dt[idx] = (acc > 20.f) ? acc : log1pf(expf(acc));
}

// ---------------- SSM scan: one (b,d) per 16-lane half-warp, lane = state s ----
__global__ void ssm_kernel(const float* __restrict__ Alog, const float* __restrict__ Dp){
  int lane = threadIdx.x & 31;
  int s = lane & 15;
  int hw = threadIdx.x >> 4;                 // half-warp index within block
  int pair = blockIdx.x*8 + hw;              // blockDim = 128 -> 8 half-warps
  int d = pair & (DI-1); int b = pair >> 9;
  float As = -expf(Alog[d*DS + s]);
  float Dv = Dp[d];
  float hst = 0.f;
  const float* ub   = g_u   + (size_t)b*LL*DI + d;
  const float* dtb  = g_dt  + (size_t)b*LL*DI + d;
  const float* dbcb = g_dbc + (size_t)b*LL*48;
  float* yb = g_y + (size_t)b*LL*DI + d;
  for (int tt=0; tt<LL; tt++){
    float delta = dtb[(size_t)tt*DI];
    float uv    = ub[(size_t)tt*DI];
    float Bm = dbcb[tt*48 + DTRN + s];
    float Cm = dbcb[tt*48 + DTRN + DS + s];
    hst = fmaf(expf(delta*As), hst, (delta*uv)*Bm);
    float val = hst*Cm;
    val += __shfl_xor_sync(0xffffffffu, val, 8, 16);
    val += __shfl_xor_sync(0xffffffffu, val, 4, 16);
    val += __shfl_xor_sync(0xffffffffu, val, 2, 16);
    val += __shfl_xor_sync(0xffffffffu, val, 1, 16);
    if (s == 0) yb[(size_t)tt*DI] = val + uv*Dv;
  }
}

// ---------------- gating: yg = y * silu(z) ----------------
__global__ void gate_kernel(){
  int idx = blockIdx.x*blockDim.x + threadIdx.x;  // NTOK*DI
  int d = idx & (DI-1); int tok = idx >> 9;
  g_yg[idx] = g_y[idx] * siluf(g_xz[(size_t)tok*XZW + DI + d]);
}

// ---------------- feat[b,e,hp,wp] = h[b, hp*16+wp, e] ----------------
__global__ void feat_kernel(){
  int idx = blockIdx.x*blockDim.x + threadIdx.x;  // B*E*16*16
  int wp = idx & 15; int t1 = idx >> 4; int hp = t1 & 15; int t2 = t1 >> 4;
  int e = t2 & 255; int b = t2 >> 8;
  g_feat[idx] = g_h[((size_t)(b*LL) + hp*HPN + wp)*EE + e];
}

// ---------------- ConvTranspose2d (stride 2, kernel 2): thread per output elem ----
__global__ void convt_kernel(const float* __restrict__ x, const float* __restrict__ w,
                             const float* __restrict__ bias, float* __restrict__ out,
                             int C, int O, int Hin, int Win, int total, int do_gelu){
  int idx = blockIdx.x*blockDim.x + threadIdx.x;
  if (idx >= total) return;
  int Wout = Win*2, Hout = Hin*2;
  int W_ = idx % Wout; int tmp = idx / Wout;
  int H_ = tmp % Hout; tmp /= Hout;
  int o = tmp % O; int b = tmp / O;
  int hh = H_ >> 1, p = H_ & 1, ww = W_ >> 1, q = W_ & 1;
  const float* xb = x + ((size_t)(b*C)*Hin + hh)*Win + ww;
  const float* wb = w + ((size_t)o*2 + p)*2 + q;
  float acc = bias[o];
  int stx = Hin*Win, stw = O*4;
  for (int c=0;c<C;c++) acc = fmaf(xb[(size_t)c*stx], wb[(size_t)c*stw], acc);
  if (do_gelu) acc = geluf(acc);
  out[idx] = acc;
}

// ---------------- launch ----------------
extern "C" void kernel_launch(void* const* d_in, const int* in_sizes, int n_in,
                              void* d_out, int out_size){
  const float* x       = (const float*)d_in[0];
  const int*   t       = (const int*)d_in[1];
  const float* time_w1 = (const float*)d_in[2];
  const float* time_b1 = (const float*)d_in[3];
  const float* time_w2 = (const float*)d_in[4];
  const float* time_b2 = (const float*)d_in[5];
  const float* patch_w = (const float*)d_in[6];
  const float* patch_b = (const float*)d_in[7];
  const float* pos     = (const float*)d_in[8];
  const float* ln_g    = (const float*)d_in[9];
  const float* ln_b    = (const float*)d_in[10];
  const float* in_proj = (const float*)d_in[11];
  const float* conv_w  = (const float*)d_in[12];
  const float* conv_b  = (const float*)d_in[13];
  const float* x_proj  = (const float*)d_in[14];
  const float* dt_w    = (const float*)d_in[15];
  const float* dt_b    = (const float*)d_in[16];
  const float* A_log   = (const float*)d_in[17];
  const float* Dp      = (const float*)d_in[18];
  const float* out_proj= (const float*)d_in[19];
  const float* dw1 = (const float*)d_in[20];
  const float* db1 = (const float*)d_in[21];
  const float* dw2 = (const float*)d_in[22];
  const float* db2 = (const float*)d_in[23];
  const float* dw3 = (const float*)d_in[24];
  const float* db3 = (const float*)d_in[25];
  const float* dw4 = (const float*)d_in[26];
  const float* db4 = (const float*)d_in[27];

  float *p_patches,*p_h,*p_hn,*p_xz,*p_u,*p_dbc,*p_yg,*p_feat,*p_d1,*p_d2,*p_d3;
  cudaGetSymbolAddress((void**)&p_patches, g_patches);
  cudaGetSymbolAddress((void**)&p_h, g_h);
  cudaGetSymbolAddress((void**)&p_hn, g_hn);
  cudaGetSymbolAddress((void**)&p_xz, g_xz);
  cudaGetSymbolAddress((void**)&p_u, g_u);
  cudaGetSymbolAddress((void**)&p_dbc, g_dbc);
  cudaGetSymbolAddress((void**)&p_yg, g_yg);
  cudaGetSymbolAddress((void**)&p_feat, g_feat);
  cudaGetSymbolAddress((void**)&p_d1, g_d1);
  cudaGetSymbolAddress((void**)&p_d2, g_d2);
  cudaGetSymbolAddress((void**)&p_d3, g_d3);

  time_emb_kernel<<<BB, EE>>>(t, time_w1, time_b1, time_w2, time_b2);
  patch_gather_kernel<<<(NTOK*512)/256, 256>>>(x);
  gemm_nt_kernel<<<dim3(EE/GBN, NTOK/GBM), 256>>>(p_patches, patch_w, nullptr, patch_b, p_h, NTOK, EE, 512);
  addpos_kernel<<<(NTOK*EE)/256, 256>>>(pos);

  for (int i=0;i<DEPTH;i++){
    ln_kernel<<<NTOK, EE>>>(ln_g + (size_t)i*EE, ln_b + (size_t)i*EE);
    gemm_nt_kernel<<<dim3(XZW/GBN, NTOK/GBM), 256>>>(p_hn, in_proj + (size_t)i*XZW*EE,
                                                     nullptr, nullptr, p_xz, NTOK, XZW, EE);
    conv_silu_kernel<<<(NTOK*DI)/256, 256>>>(conv_w + (size_t)i*DI*DCN, conv_b + (size_t)i*DI);
    gemm_nt_kernel<<<dim3(1, NTOK/GBM), 256>>>(p_u, x_proj + (size_t)i*48*DI,
                                               nullptr, nullptr, p_dbc, NTOK, 48, DI);
    dt_kernel<<<(NTOK*DI)/256, 256>>>(dt_w + (size_t)i*DI*DTRN, dt_b + (size_t)i*DI);
    ssm_kernel<<<(BB*DI)/8, 128>>>(A_log + (size_t)i*DI*DS, Dp + (size_t)i*DI);
    gate_kernel<<<(NTOK*DI)/256, 256>>>();
    gemm_nt_kernel<<<dim3(EE/GBN, NTOK/GBM), 256>>>(p_yg, out_proj + (size_t)i*EE*DI,
                                                    p_h, nullptr, p_h, NTOK, EE, DI);
  }

  feat_kernel<<<(NTOK*EE)/256, 256>>>();
  convt_kernel<<<(BB*128*32*32)/256, 256>>>(p_feat, dw1, db1, p_d1, 256, 128, 16, 16, BB*128*32*32, 1);
  convt_kernel<<<(BB*64*64*64)/256, 256>>>(p_d1, dw2, db2, p_d2, 128, 64, 32, 32, BB*64*64*64, 1);
  convt_kernel<<<(BB*32*128*128)/256, 256>>>(p_d2, dw3, db3, p_d3, 64, 32, 64, 64, BB*32*128*128, 1);
  convt_kernel<<<(BB*256*256)/256, 256>>>(p_d3, dw4, db4, (float*)d_out, 32, 1, 128, 128, BB*256*256, 0);
}